// round 12
// baseline (speedup 1.0000x reference)
#include <cuda_runtime.h>

#define BB 8
#define CC 32
#define HH 384
#define WW 768
#define HW  (HH * WW)
#define CHW ((size_t)CC * HH * WW)
#define CPI 4
#define NIT (CC / CPI)
#define TPB 384                      // 2 pixels per thread

__global__ __launch_bounds__(TPB)
void disparity_warp_k12(const float* __restrict__ src,
                        const float* __restrict__ disp,
                        float* __restrict__ out) {
    __shared__ float tmp[2][CPI][WW];   // double-buffered vert-interpolated rows (24 KB)

    const int t2 = threadIdx.x;         // 0..383 -> pixels 2*t2, 2*t2+1
    const int h  = blockIdx.x % HH;
    const int b  = blockIdx.x / HH;

    // ---- vertical coords: uniform per block ----
    const float iy  = (float)h * (384.0f / 383.0f) - 0.5f;
    const float y0f = floorf(iy);
    const float fy  = iy - y0f;
    const int   y0  = (int)y0f, y1 = y0 + 1;
    const float wy0 = (1.0f - fy) * (((y0 >= 0) & (y0 < HH)) ? 1.0f : 0.0f);
    const float wy1 = fy          * (((y1 >= 0) & (y1 < HH)) ? 1.0f : 0.0f);
    const int   cy0 = min(max(y0, 0), HH - 1);
    const int   cy1 = min(max(y1, 0), HH - 1);

    // ---- horizontal coords: 2 pixels per thread, vector disp load ----
    const float2 dv = *(const float2*)(disp + (size_t)(b * HH + h) * WW + 2 * t2);

    int   cx0[2], cx1[2];
    float wx0[2], wx1[2];
    #pragma unroll
    for (int i = 0; i < 2; ++i) {
        const int   wp  = 2 * t2 + i;
        const float d   = (i == 0) ? dv.x : dv.y;
        const float ix  = ((float)wp - d) * (768.0f / 767.0f) - 0.5f;
        const float x0f = floorf(ix);
        const float fx  = ix - x0f;
        const int   x0  = (int)x0f, x1 = x0 + 1;
        wx0[i] = (1.0f - fx) * (((x0 >= 0) & (x0 < WW)) ? 1.0f : 0.0f);
        wx1[i] = fx          * (((x1 >= 0) & (x1 < WW)) ? 1.0f : 0.0f);
        cx0[i] = min(max(x0, 0), WW - 1);
        cx1[i] = min(max(x1, 0), WW - 1);
    }

    // coalesced float2 row pointers (8B-aligned: all offsets even)
    const float* r0 = src + (size_t)b * CHW + (size_t)cy0 * WW + 2 * t2;
    const float* r1 = src + (size_t)b * CHW + (size_t)cy1 * WW + 2 * t2;
    float*       ob = out + (size_t)b * CHW + (size_t)h  * WW + 2 * t2;

    #pragma unroll
    for (int it = 0; it < NIT; ++it) {
        const int buf = it & 1;

        // phase 1: vectorized vertical interp -> smem
        #pragma unroll
        for (int cc = 0; cc < CPI; ++cc) {
            const int c = it * CPI + cc;
            const float2 A0 = *(const float2*)(r0 + (size_t)c * HW);
            const float2 A1 = *(const float2*)(r1 + (size_t)c * HW);
            float2 v;
            v.x = A0.x * wy0 + A1.x * wy1;
            v.y = A0.y * wy0 + A1.y * wy1;
            *(float2*)&tmp[buf][cc][2 * t2] = v;
        }

        __syncthreads();

        // phase 2: horizontal interp (scalar LDS), vectorized store
        #pragma unroll
        for (int cc = 0; cc < CPI; ++cc) {
            const int c = it * CPI + cc;
            const float* row = tmp[buf][cc];
            float2 r;
            r.x = row[cx0[0]] * wx0[0] + row[cx1[0]] * wx1[0];
            r.y = row[cx0[1]] * wx0[1] + row[cx1[1]] * wx1[1];
            *(float2*)(ob + (size_t)c * HW) = r;
        }
        // double buffer: smem reuse separated by next iteration's barrier
    }
}

extern "C" void kernel_launch(void* const* d_in, const int* in_sizes, int n_in,
                              void* d_out, int out_size) {
    const float* src  = (const float*)d_in[0];
    const float* disp = (const float*)d_in[1];
    float* out = (float*)d_out;

    disparity_warp_k12<<<BB * HH, TPB>>>(src, disp, out);
}

// round 13
// speedup vs baseline: 1.0388x; 1.0388x over previous
#include <cuda_runtime.h>

#define BB 8
#define CC 32
#define HH 384
#define WW 768
#define HW  (HH * WW)
#define CHW ((size_t)CC * HH * WW)
#define CPI 4                        // channels per iteration

__global__ __launch_bounds__(768)
void disparity_warp_k13(const float* __restrict__ src,
                        const float* __restrict__ disp,
                        float* __restrict__ out) {
    __shared__ float tmp[2][CPI][WW];   // double-buffered vert-interpolated rows

    const int w = threadIdx.x;          // 0..767
    const int h = blockIdx.x % HH;
    const int b = blockIdx.x / HH;

    // ---- vertical coords: uniform per block ----
    const float iy  = (float)h * (384.0f / 383.0f) - 0.5f;
    const float y0f = floorf(iy);
    const float fy  = iy - y0f;
    const int   y0  = (int)y0f, y1 = y0 + 1;
    const float wy0 = (1.0f - fy) * (((y0 >= 0) & (y0 < HH)) ? 1.0f : 0.0f);
    const float wy1 = fy          * (((y1 >= 0) & (y1 < HH)) ? 1.0f : 0.0f);
    const int   cy0 = min(max(y0, 0), HH - 1);
    const int   cy1 = min(max(y1, 0), HH - 1);

    // ---- horizontal coords: per-thread (disp read once -> streaming load) ----
    const float d   = __ldcs(disp + (size_t)(b * HH + h) * WW + w);
    const float ix  = ((float)w - d) * (768.0f / 767.0f) - 0.5f;
    const float x0f = floorf(ix);
    const float fx  = ix - x0f;
    const int   x0  = (int)x0f, x1 = x0 + 1;
    const float wx0 = (1.0f - fx) * (((x0 >= 0) & (x0 < WW)) ? 1.0f : 0.0f);
    const float wx1 = fx          * (((x1 >= 0) & (x1 < WW)) ? 1.0f : 0.0f);
    const int   cx0 = min(max(x0, 0), WW - 1);
    const int   cx1 = min(max(x1, 0), WW - 1);

    const float* r0 = src + (size_t)b * CHW + (size_t)cy0 * WW + w;  // coalesced
    const float* r1 = src + (size_t)b * CHW + (size_t)cy1 * WW + w;  // coalesced
    float* ob = out + (size_t)b * CHW + (size_t)h * WW + w;

    #pragma unroll
    for (int it = 0; it < CC / CPI; ++it) {
        const int buf = it & 1;

        // phase 1: vertical interp, fully coalesced (8 LDG in flight)
        float v[CPI];
        #pragma unroll
        for (int cc = 0; cc < CPI; ++cc) {
            const int c = it * CPI + cc;
            const float a0 = r0[(size_t)c * HW];
            const float a1 = r1[(size_t)c * HW];
            v[cc] = a0 * wy0 + a1 * wy1;
        }
        #pragma unroll
        for (int cc = 0; cc < CPI; ++cc)
            tmp[buf][cc][w] = v[cc];

        __syncthreads();

        // phase 2: horizontal interp from shared row; streaming (evict-first)
        // stores keep the reusable src rows resident in L2.
        #pragma unroll
        for (int cc = 0; cc < CPI; ++cc) {
            const int c = it * CPI + cc;
            const float t = tmp[buf][cc][cx0] * wx0 + tmp[buf][cc][cx1] * wx1;
            __stcs(ob + (size_t)c * HW, t);
        }
        // double buffer: smem reuse separated by the next iteration's barrier
    }
}

extern "C" void kernel_launch(void* const* d_in, const int* in_sizes, int n_in,
                              void* d_out, int out_size) {
    const float* src  = (const float*)d_in[0];
    const float* disp = (const float*)d_in[1];
    float* out = (float*)d_out;

    disparity_warp_k13<<<BB * HH, 768>>>(src, disp, out);
}